// round 16
// baseline (speedup 1.0000x reference)
#include <cuda_runtime.h>
#include <cuda_fp16.h>
#include <math.h>
#include <stdint.h>

// Problem constants
#define BATCH 8
#define SEQ   2048
#define FEAT  1024
#define KD    512
#define VD    512
#define OUTD  1536   // FEAT + VD
#define MROWS (BATCH * SEQ)   // 16384

// Scratch (device globals; no allocations allowed)
__device__ __half g_xh[MROWS * FEAT];           // x in fp16
__device__ __half g_wt[3 * KD * FEAT];          // Wq/Wk/Wv transposed [n, k] fp16
__device__ __half g_qh[MROWS * KD];
__device__ __half g_kh[MROWS * KD];
__device__ __half g_vt[VD * MROWS];             // v transposed: [vd, b*S]
__device__ __half g_logits[BATCH * SEQ * SEQ];  // fp16 logits
__device__ __half g_ph[BATCH * SEQ * SEQ];      // unnormalized probs fp16
__device__ float  g_rsum[MROWS];                // 1/rowsum

// 3-stage smem: per stage, A = 128 rows x 32 words (16KB) + B same (16KB)
#define STAGE_WORDS 8192
#define STAGE_BYTES (STAGE_WORDS * 4)
#define SMEM_BYTES  (3 * STAGE_BYTES)           // 96 KB

#define NTHREADS 512

__device__ __forceinline__ void cp16(uint32_t* dst, const void* src) {
    uint32_t a = (uint32_t)__cvta_generic_to_shared(dst);
    asm volatile("cp.async.cg.shared.global [%0], [%1], 16;\n" :: "r"(a), "l"(src));
}
__device__ __forceinline__ void cp_commit() {
    asm volatile("cp.async.commit_group;\n" ::: "memory");
}
__device__ __forceinline__ void cp_wait1() {
    asm volatile("cp.async.wait_group 1;\n" ::: "memory");
}
__device__ __forceinline__ void ldsm4(uint32_t* r, uint32_t addr) {
    asm volatile("ldmatrix.sync.aligned.m8n8.x4.shared.b16 {%0,%1,%2,%3}, [%4];"
        : "=r"(r[0]), "=r"(r[1]), "=r"(r[2]), "=r"(r[3]) : "r"(addr));
}
__device__ __forceinline__ void ldsm2(uint32_t* r, uint32_t addr) {
    asm volatile("ldmatrix.sync.aligned.m8n8.x2.shared.b16 {%0,%1}, [%2];"
        : "=r"(r[0]), "=r"(r[1]) : "r"(addr));
}

// ---------------------------------------------------------------------------
// fp16 tensor-core GEMM (mma m16n8k16, fp32 accum), ldmatrix fragment loads.
// CTA tile 128x128, 512 threads, warp grid 4(M)x4(N), warp tile 32x32,
// BK=64 halfs, 3-stage cp.async, XOR-swizzled smem, 2 CTAs/SM (32 warps).
// A row-major [M,K], B n-major [N,K].
// MODE 0: fused QKV. z in {0,1,2}: C=qh / C1=kh / C2=vt (transposed store).
// MODE 1: QK^T -> fp16 logits * alpha. Triangular 1D grid.
// MODE 2: PV (A=probs fp16, B=vt). Causal K clamp, rowscale epilogue, fp32 out.
// ---------------------------------------------------------------------------
template<int MODE>
__global__ __launch_bounds__(NTHREADS, 2) void mma_gemm(
    const __half* __restrict__ A,
    const __half* __restrict__ B,
    const float* __restrict__ bias0,
    const float* __restrict__ bias1,
    const float* __restrict__ bias2,
    const float* __restrict__ rowscale,
    void* __restrict__ Cv,
    void* __restrict__ C1v,
    void* __restrict__ C2v,
    int lda, int ldb, int ldc, int K,
    long long sA, long long sB, long long sC,
    float alpha)
{
    constexpr bool CAUSAL_K = (MODE == 2);

    int m0, n0;
    if (MODE == 1) {
        const int t = blockIdx.x;
        int i = (int)((sqrtf(8.0f * (float)t + 1.0f) - 1.0f) * 0.5f);
        if ((i + 1) * (i + 2) / 2 <= t) i++;
        if (i * (i + 1) / 2 > t) i--;
        const int j = t - i * (i + 1) / 2;
        m0 = i * 128;
        n0 = j * 128;
    } else {
        m0 = blockIdx.y * 128;
        n0 = blockIdx.x * 128;
    }

    const int z = blockIdx.z;
    const float* bias = bias0;
    if (MODE == 0) {
        B += (long long)z * KD * FEAT;          // Wt slice
        if (z == 1) bias = bias1;
        if (z == 2) bias = bias2;
    } else {
        A += (long long)z * sA;
        B += (long long)z * sB;
        if (MODE == 2) rowscale += (long long)z * SEQ;
    }

    const int K_end = CAUSAL_K ? (K < m0 + 128 ? K : m0 + 128) : K;
    const int n_iter = K_end >> 6;

    extern __shared__ uint32_t smem[];

    const int tid  = threadIdx.x;
    const int lane = tid & 31;
    const int w    = tid >> 5;
    const int wm   = w & 3;       // 0..3 (M)
    const int wn   = w >> 2;      // 0..3 (N)

    // XOR-swizzled staging: word (r,c) -> r*32 + (c ^ ((r&7)<<2)), c in [0,32)
    auto load_tile = [&](int k0, int s) {
        uint32_t* Sa = smem + s * STAGE_WORDS;
        uint32_t* Sb = Sa + 4096;
        #pragma unroll
        for (int i = 0; i < 2; i++) {
            const int idx = tid + i * NTHREADS;
            const int r   = idx >> 3;
            const int c4  = (idx & 7) << 2;            // word offset
            cp16(&Sa[r * 32 + (c4 ^ ((r & 7) << 2))],
                 &A[(long long)(m0 + r) * lda + k0 + (c4 << 1)]);
        }
        #pragma unroll
        for (int i = 0; i < 2; i++) {
            const int idx = tid + i * NTHREADS;
            const int r   = idx >> 3;
            const int c4  = (idx & 7) << 2;
            cp16(&Sb[r * 32 + (c4 ^ ((r & 7) << 2))],
                 &B[(long long)(n0 + r) * ldb + k0 + (c4 << 1)]);
        }
    };

    // ldmatrix per-lane constants
    const uint32_t sbase  = (uint32_t)__cvta_generic_to_shared(smem);
    const uint32_t maskB  = (uint32_t)((lane & 7) << 2);           // word-space swizzle mask
    const uint32_t abase0 = sbase + (uint32_t)((wm * 32 + (lane & 15)) * 128);
    const uint32_t bbase0 = sbase + 16384u + (uint32_t)((wn * 32 + (lane & 7)) * 128);
    const uint32_t cA = (uint32_t)((lane & 16) >> 2);              // 0 or 4 words
    const uint32_t cB = (uint32_t)((lane & 8) >> 1);               // 0 or 4 words

    float acc[2][4][4];
    #pragma unroll
    for (int i = 0; i < 2; i++)
        #pragma unroll
        for (int j = 0; j < 4; j++)
            #pragma unroll
            for (int r = 0; r < 4; r++) acc[i][j][r] = 0.0f;

    load_tile(0, 0);
    cp_commit();
    if (1 < n_iter) load_tile(64, 1);
    cp_commit();

    int s = 0, ls = 2;
    for (int it = 0; it < n_iter; it++) {
        cp_wait1();
        __syncthreads();

        if (it + 2 < n_iter) load_tile((it + 2) << 6, ls);
        cp_commit();

        const uint32_t soff = (uint32_t)(s * STAGE_BYTES);

        #pragma unroll
        for (int ks = 0; ks < 4; ks++) {      // 4 x k16 steps = 64 halfs
            const uint32_t kk = (uint32_t)(ks * 8);   // word offset of this step
            const uint32_t offA = ((kk + cA) ^ maskB) << 2;   // byte offset in row
            const uint32_t offB = ((kk + cB) ^ maskB) << 2;
            uint32_t a[2][4];
            uint32_t b[4][2];
            #pragma unroll
            for (int tm = 0; tm < 2; tm++)
                ldsm4(a[tm], abase0 + soff + (uint32_t)(tm * 2048) + offA);
            #pragma unroll
            for (int tn = 0; tn < 4; tn++)
                ldsm2(b[tn], bbase0 + soff + (uint32_t)(tn * 1024) + offB);
            #pragma unroll
            for (int tm = 0; tm < 2; tm++)
                #pragma unroll
                for (int tn = 0; tn < 4; tn++) {
                    asm volatile(
                        "mma.sync.aligned.m16n8k16.row.col.f32.f16.f16.f32 "
                        "{%0,%1,%2,%3}, {%4,%5,%6,%7}, {%8,%9}, {%0,%1,%2,%3};\n"
                        : "+f"(acc[tm][tn][0]), "+f"(acc[tm][tn][1]),
                          "+f"(acc[tm][tn][2]), "+f"(acc[tm][tn][3])
                        : "r"(a[tm][0]), "r"(a[tm][1]), "r"(a[tm][2]), "r"(a[tm][3]),
                          "r"(b[tn][0]), "r"(b[tn][1]));
                }
        }
        s  = (s  == 2) ? 0 : s + 1;
        ls = (ls == 2) ? 0 : ls + 1;
    }

    // ---- epilogue ----
    const int l4 = lane >> 2;
    const int lm = lane & 3;
    #pragma unroll
    for (int tm = 0; tm < 2; tm++) {
        const int row = m0 + wm * 32 + tm * 16 + l4;
        float f0 = alpha, f1 = alpha;
        if (MODE == 2) { f0 = alpha * rowscale[row]; f1 = alpha * rowscale[row + 8]; }
        #pragma unroll
        for (int tn = 0; tn < 4; tn++) {
            const int col = n0 + wn * 32 + tn * 8 + (lm << 1);
            if (MODE == 0) {
                const float bx = bias[col], by = bias[col + 1];
                const float v0x = acc[tm][tn][0] + bx, v0y = acc[tm][tn][1] + by;
                const float v1x = acc[tm][tn][2] + bx, v1y = acc[tm][tn][3] + by;
                if (z < 2) {
                    __half* O = (__half*)(z ? C1v : Cv);
                    *(__half2*)&O[(long long)row * KD + col] = __floats2half2_rn(v0x, v0y);
                    *(__half2*)&O[(long long)(row + 8) * KD + col] = __floats2half2_rn(v1x, v1y);
                } else {
                    __half* T = (__half*)C2v;    // [VD][MROWS]
                    T[(long long)col * MROWS + row]           = __float2half_rn(v0x);
                    T[(long long)(col + 1) * MROWS + row]     = __float2half_rn(v0y);
                    T[(long long)col * MROWS + row + 8]       = __float2half_rn(v1x);
                    T[(long long)(col + 1) * MROWS + row + 8] = __float2half_rn(v1y);
                }
            } else if (MODE == 1) {
                __half* O = (__half*)Cv + (long long)z * sC;
                *(__half2*)&O[(long long)row * ldc + col] =
                    __floats2half2_rn(acc[tm][tn][0] * f0, acc[tm][tn][1] * f0);
                *(__half2*)&O[(long long)(row + 8) * ldc + col] =
                    __floats2half2_rn(acc[tm][tn][2] * f1, acc[tm][tn][3] * f1);
            } else {
                float* O = (float*)Cv + (long long)z * sC;
                float2 v0, v1;
                v0.x = acc[tm][tn][0] * f0;
                v0.y = acc[tm][tn][1] * f0;
                v1.x = acc[tm][tn][2] * f1;
                v1.y = acc[tm][tn][3] * f1;
                *(float2*)&O[(long long)row * ldc + col]       = v0;
                *(float2*)&O[(long long)(row + 8) * ldc + col] = v1;
            }
        }
    }
}

// ---------------------------------------------------------------------------
// Prep: W[k][n] fp32 -> Wt[z][n][k] fp16, tiled smem transpose (coalesced R+W)
// grid: (KD/32, FEAT/32, 3), block: 32x8
// ---------------------------------------------------------------------------
__global__ __launch_bounds__(256) void cvt_w_kernel(const float* __restrict__ Wq,
                                                    const float* __restrict__ Wk,
                                                    const float* __restrict__ Wv,
                                                    __half* __restrict__ Wt)
{
    __shared__ float tile[32][33];
    const int zz = blockIdx.z;
    const float* W = (zz == 0) ? Wq : (zz == 1) ? Wk : Wv;
    __half* T = Wt + (long long)zz * KD * FEAT;

    const int n0 = blockIdx.x * 32;       // n block
    const int r0 = blockIdx.y * 32;       // k block
    const int tx = threadIdx.x;           // 0..31
    const int ty = threadIdx.y;           // 0..7

    #pragma unroll
    for (int j = 0; j < 4; j++) {
        const int r = ty + j * 8;
        tile[r][tx] = W[(long long)(r0 + r) * KD + n0 + tx];   // coalesced read
    }
    __syncthreads();
    #pragma unroll
    for (int j = 0; j < 4; j++) {
        const int n = ty + j * 8;
        T[(long long)(n0 + n) * FEAT + r0 + tx] = __float2half_rn(tile[tx][n]);  // coalesced write
    }
}

// ---------------------------------------------------------------------------
// Fused: copy x into out[..., 0:FEAT] AND convert x -> fp16 (one read of x)
// ---------------------------------------------------------------------------
__global__ __launch_bounds__(256) void copy_cvt_kernel(const float4* __restrict__ x,
                                                       float4* __restrict__ out,
                                                       uint2* __restrict__ xh)
{
    const long long i = (long long)blockIdx.x * blockDim.x + threadIdx.x;
    const long long total = (long long)MROWS * (FEAT / 4);
    if (i >= total) return;
    const long long row = i / (FEAT / 4);
    const int col = (int)(i % (FEAT / 4));
    float4 v = x[i];
    out[row * (OUTD / 4) + col] = v;
    __half2 h0 = __floats2half2_rn(v.x, v.y);
    __half2 h1 = __floats2half2_rn(v.z, v.w);
    uint2 u;
    u.x = *(uint32_t*)&h0;
    u.y = *(uint32_t*)&h1;
    xh[i] = u;
}

// ---------------------------------------------------------------------------
// Warp-per-row softmax over fp16 logits: max pass + exp pass (fp32 math),
// writes unnormalized fp16 probs (zeros fused to 128-aligned band end);
// rsum = 1/sum.
// ---------------------------------------------------------------------------
__global__ __launch_bounds__(256) void softmax_kernel(const __half* __restrict__ logits,
                                                      __half* __restrict__ probs,
                                                      float* __restrict__ rsum)
{
    const int wid  = threadIdx.x >> 5;
    const int lane = threadIdx.x & 31;
    const long long row = (long long)blockIdx.x * 8 + wid;
    const int q = (int)(row % SEQ);
    const __half* p = logits + row * SEQ;
    const uint2* p4 = (const uint2*)p;              // 4 halfs per element
    uint2* o4 = (uint2*)(probs + row * SEQ);        // 4 halfs per element
    const int len  = q + 1;
    const int len4 = len >> 2;
    const int band4 = (((q >> 7) + 1) << 7) >> 2;   // groups of 4, multiple of 32

    float mx = -INFINITY;
    for (int i = lane; i < len4; i += 32) {
        uint2 u = p4[i];
        const float2 f0 = __half22float2(*(const __half2*)&u.x);
        const float2 f1 = __half22float2(*(const __half2*)&u.y);
        mx = fmaxf(mx, fmaxf(fmaxf(f0.x, f0.y), fmaxf(f1.x, f1.y)));
    }
    for (int i = (len4 << 2) + lane; i < len; i += 32)
        mx = fmaxf(mx, __half2float(p[i]));
    #pragma unroll
    for (int o = 16; o > 0; o >>= 1)
        mx = fmaxf(mx, __shfl_xor_sync(0xffffffffu, mx, o));

    float sum = 0.0f;
    for (int i = lane; i < band4; i += 32) {
        uint2 u = p4[i];
        const float2 f0 = __half22float2(*(const __half2*)&u.x);
        const float2 f1 = __half22float2(*(const __half2*)&u.y);
        const int e = i << 2;
        float w0 = (e     < len) ? __expf(f0.x - mx) : 0.0f;
        float w1 = (e + 1 < len) ? __expf(f0.y - mx) : 0.0f;
        float w2 = (e + 2 < len) ? __expf(f1.x - mx) : 0.0f;
        float w3 = (e + 3 < len) ? __expf(f1.y - mx) : 0.0f;
        sum += (w0 + w1) + (w2 + w3);
        __half2 h0 = __floats2half2_rn(w0, w1);
        __half2 h1 = __floats2half2_rn(w2, w3);
        uint2 o;
        o.x = *(uint32_t*)&h0;
        o.y = *(uint32_t*)&h1;
        o4[i] = o;
    }
    #pragma unroll
    for (int o = 16; o > 0; o >>= 1)
        sum += __shfl_xor_sync(0xffffffffu, sum, o);

    if (lane == 0) rsum[row] = 1.0f / sum;
}

// ---------------------------------------------------------------------------
extern "C" void kernel_launch(void* const* d_in, const int* in_sizes, int n_in,
                              void* d_out, int out_size)
{
    const float* x  = (const float*)d_in[0];
    const float* Wq = (const float*)d_in[1];
    const float* bq = (const float*)d_in[2];
    const float* Wk = (const float*)d_in[3];
    const float* bk = (const float*)d_in[4];
    const float* Wv = (const float*)d_in[5];
    const float* bv = (const float*)d_in[6];
    float* out = (float*)d_out;

    __half *xh, *wt, *qh, *kh, *vt, *ph, *logits;
    float *rsum;
    cudaGetSymbolAddress((void**)&xh,     g_xh);
    cudaGetSymbolAddress((void**)&wt,     g_wt);
    cudaGetSymbolAddress((void**)&qh,     g_qh);
    cudaGetSymbolAddress((void**)&kh,     g_kh);
    cudaGetSymbolAddress((void**)&vt,     g_vt);
    cudaGetSymbolAddress((void**)&ph,     g_ph);
    cudaGetSymbolAddress((void**)&logits, g_logits);
    cudaGetSymbolAddress((void**)&rsum,   g_rsum);

    const float scale = 0.044194173824159216f;  // 1/sqrt(512)

    cudaFuncSetAttribute(mma_gemm<0>, cudaFuncAttributeMaxDynamicSharedMemorySize, SMEM_BYTES);
    cudaFuncSetAttribute(mma_gemm<1>, cudaFuncAttributeMaxDynamicSharedMemorySize, SMEM_BYTES);
    cudaFuncSetAttribute(mma_gemm<2>, cudaFuncAttributeMaxDynamicSharedMemorySize, SMEM_BYTES);

    // prep: x copy+convert (one read), W tiled transpose+convert
    copy_cvt_kernel<<<(int)(((long long)MROWS * (FEAT / 4) + 255) / 256), 256>>>(
        (const float4*)x, (float4*)out, (uint2*)xh);
    {
        dim3 grid(KD / 32, FEAT / 32, 3);
        dim3 blk(32, 8, 1);
        cvt_w_kernel<<<grid, blk>>>(Wq, Wk, Wv, wt);
    }

    // Fused QKV projections (z: q / k / v-transposed)
    {
        dim3 grid(KD / 128, MROWS / 128, 3);
        mma_gemm<0><<<grid, NTHREADS, SMEM_BYTES>>>(
            xh, wt, bq, bk, bv, nullptr, qh, kh, vt,
            FEAT, FEAT, 0, FEAT, 0, 0, 0, 1.0f);
    }

    // logits(fp16) = scale * Q @ K^T : triangular grid
    {
        dim3 grid(136, 1, BATCH);
        mma_gemm<1><<<grid, NTHREADS, SMEM_BYTES>>>(
            qh, kh, nullptr, nullptr, nullptr, nullptr, logits, nullptr, nullptr,
            KD, KD, SEQ, KD,
            (long long)SEQ * KD, (long long)SEQ * KD, (long long)SEQ * SEQ, scale);
    }

    // softmax: fp16 logits -> fp16 unnormalized probs (+band zero), 1/sum
    softmax_kernel<<<MROWS / 8, 256>>>(logits, ph, rsum);

    // read = (P @ V) * rowscale -> out[..., FEAT:]
    {
        dim3 grid(VD / 128, SEQ / 128, BATCH);
        mma_gemm<2><<<grid, NTHREADS, SMEM_BYTES>>>(
            ph, vt, nullptr, nullptr, nullptr, rsum, out + FEAT, nullptr, nullptr,
            SEQ, MROWS, OUTD, SEQ,
            (long long)SEQ * SEQ, SEQ, (long long)SEQ * OUTD, 1.0f);
    }
}

// round 17
// speedup vs baseline: 1.1636x; 1.1636x over previous
#include <cuda_runtime.h>
#include <cuda_fp16.h>
#include <math.h>
#include <stdint.h>

// Problem constants
#define BATCH 8
#define SEQ   2048
#define FEAT  1024
#define KD    512
#define VD    512
#define OUTD  1536   // FEAT + VD
#define MROWS (BATCH * SEQ)   // 16384

// Scratch (device globals; no allocations allowed)
__device__ __half g_xh[MROWS * FEAT];           // x in fp16
__device__ __half g_wt[3 * KD * FEAT];          // Wq/Wk/Wv transposed [n, k] fp16
__device__ __half g_qh[MROWS * KD];
__device__ __half g_kh[MROWS * KD];
__device__ __half g_vt[VD * MROWS];             // v transposed: [vd, b*S]
__device__ __half g_logits[BATCH * SEQ * SEQ];  // fp16 logits
__device__ __half g_ph[BATCH * SEQ * SEQ];      // unnormalized probs fp16
__device__ float  g_rsum[MROWS];                // 1/rowsum

// 3-stage smem: per stage, A = 128 rows x 32 words (16KB) + B same (16KB)
#define STAGE_WORDS 8192
#define STAGE_BYTES (STAGE_WORDS * 4)
#define SMEM_BYTES  (3 * STAGE_BYTES)           // 96 KB

__device__ __forceinline__ void cp16(uint32_t* dst, const void* src) {
    uint32_t a = (uint32_t)__cvta_generic_to_shared(dst);
    asm volatile("cp.async.cg.shared.global [%0], [%1], 16;\n" :: "r"(a), "l"(src));
}
__device__ __forceinline__ void cp_commit() {
    asm volatile("cp.async.commit_group;\n" ::: "memory");
}
__device__ __forceinline__ void cp_wait1() {
    asm volatile("cp.async.wait_group 1;\n" ::: "memory");
}
__device__ __forceinline__ void ldsm4(uint32_t* r, uint32_t addr) {
    asm volatile("ldmatrix.sync.aligned.m8n8.x4.shared.b16 {%0,%1,%2,%3}, [%4];"
        : "=r"(r[0]), "=r"(r[1]), "=r"(r[2]), "=r"(r[3]) : "r"(addr));
}
__device__ __forceinline__ void ldsm2(uint32_t* r, uint32_t addr) {
    asm volatile("ldmatrix.sync.aligned.m8n8.x2.shared.b16 {%0,%1}, [%2];"
        : "=r"(r[0]), "=r"(r[1]) : "r"(addr));
}

// ---------------------------------------------------------------------------
// fp16 tensor-core GEMM (mma m16n8k16, fp32 accum), ldmatrix fragment loads.
// CTA tile 128x128, warp grid 2(M)x4(N), BK=64 halfs, 3-stage cp.async,
// XOR-swizzled smem, one __syncthreads per iter, 2 CTAs/SM.
// A row-major [M,K], B n-major [N,K].
// MODE 0: fused QKV. z in {0,1,2}: C=qh / C1=kh / C2=vt (smem-staged transpose).
// MODE 1: QK^T -> fp16 logits * alpha. Triangular 1D grid.
// MODE 2: PV (A=probs fp16, B=vt). Causal K clamp, rowscale epilogue, fp32 out.
// ---------------------------------------------------------------------------
template<int MODE>
__global__ __launch_bounds__(256, 2) void mma_gemm(
    const __half* __restrict__ A,
    const __half* __restrict__ B,
    const float* __restrict__ bias0,
    const float* __restrict__ bias1,
    const float* __restrict__ bias2,
    const float* __restrict__ rowscale,
    void* __restrict__ Cv,
    void* __restrict__ C1v,
    void* __restrict__ C2v,
    int lda, int ldb, int ldc, int K,
    long long sA, long long sB, long long sC,
    float alpha)
{
    constexpr bool CAUSAL_K = (MODE == 2);

    int m0, n0;
    if (MODE == 1) {
        const int t = blockIdx.x;
        int i = (int)((sqrtf(8.0f * (float)t + 1.0f) - 1.0f) * 0.5f);
        if ((i + 1) * (i + 2) / 2 <= t) i++;
        if (i * (i + 1) / 2 > t) i--;
        const int j = t - i * (i + 1) / 2;
        m0 = i * 128;
        n0 = j * 128;
    } else {
        m0 = blockIdx.y * 128;
        n0 = blockIdx.x * 128;
    }

    const int z = blockIdx.z;
    const float* bias = bias0;
    if (MODE == 0) {
        B += (long long)z * KD * FEAT;          // Wt slice
        if (z == 1) bias = bias1;
        if (z == 2) bias = bias2;
    } else {
        A += (long long)z * sA;
        B += (long long)z * sB;
        if (MODE == 2) rowscale += (long long)z * SEQ;
    }

    const int K_end = CAUSAL_K ? (K < m0 + 128 ? K : m0 + 128) : K;
    const int n_iter = K_end >> 6;

    extern __shared__ uint32_t smem[];

    const int tid  = threadIdx.x;
    const int lane = tid & 31;
    const int w    = tid >> 5;
    const int wm   = w & 1;
    const int wn   = w >> 1;

    // XOR-swizzled staging: word (r,c) -> r*32 + (c ^ ((r&7)<<2)), c in [0,32)
    auto load_tile = [&](int k0, int s) {
        uint32_t* Sa = smem + s * STAGE_WORDS;
        uint32_t* Sb = Sa + 4096;
        #pragma unroll
        for (int i = 0; i < 4; i++) {
            const int idx = tid + i * 256;
            const int r   = idx >> 3;
            const int c4  = (idx & 7) << 2;            // word offset
            cp16(&Sa[r * 32 + (c4 ^ ((r & 7) << 2))],
                 &A[(long long)(m0 + r) * lda + k0 + (c4 << 1)]);
        }
        #pragma unroll
        for (int i = 0; i < 4; i++) {
            const int idx = tid + i * 256;
            const int r   = idx >> 3;
            const int c4  = (idx & 7) << 2;
            cp16(&Sb[r * 32 + (c4 ^ ((r & 7) << 2))],
                 &B[(long long)(n0 + r) * ldb + k0 + (c4 << 1)]);
        }
    };

    // ldmatrix per-lane constants
    const uint32_t sbase  = (uint32_t)__cvta_generic_to_shared(smem);
    const uint32_t maskB  = (uint32_t)((lane & 7) << 2);           // word-space swizzle mask
    const uint32_t abase0 = sbase + (uint32_t)((wm * 64 + (lane & 15)) * 128);
    const uint32_t bbase0 = sbase + 16384u + (uint32_t)((wn * 32 + (lane & 7)) * 128);
    const uint32_t cA = (uint32_t)((lane & 16) >> 2);              // 0 or 4 words
    const uint32_t cB = (uint32_t)((lane & 8) >> 1);               // 0 or 4 words

    float acc[4][4][4];
    #pragma unroll
    for (int i = 0; i < 4; i++)
        #pragma unroll
        for (int j = 0; j < 4; j++)
            #pragma unroll
            for (int r = 0; r < 4; r++) acc[i][j][r] = 0.0f;

    load_tile(0, 0);
    cp_commit();
    if (1 < n_iter) load_tile(64, 1);
    cp_commit();

    int s = 0, ls = 2;
    for (int it = 0; it < n_iter; it++) {
        cp_wait1();
        __syncthreads();

        if (it + 2 < n_iter) load_tile((it + 2) << 6, ls);
        cp_commit();

        const uint32_t soff = (uint32_t)(s * STAGE_BYTES);

        #pragma unroll
        for (int ks = 0; ks < 4; ks++) {      // 4 x k16 steps = 64 halfs
            const uint32_t kk = (uint32_t)(ks * 8);   // word offset of this step
            const uint32_t offA = ((kk + cA) ^ maskB) << 2;   // byte offset in row
            const uint32_t offB = ((kk + cB) ^ maskB) << 2;
            uint32_t a[4][4];
            uint32_t b[4][2];
            #pragma unroll
            for (int tm = 0; tm < 4; tm++)
                ldsm4(a[tm], abase0 + soff + (uint32_t)(tm * 2048) + offA);
            #pragma unroll
            for (int tn = 0; tn < 4; tn++)
                ldsm2(b[tn], bbase0 + soff + (uint32_t)(tn * 1024) + offB);
            #pragma unroll
            for (int tm = 0; tm < 4; tm++)
                #pragma unroll
                for (int tn = 0; tn < 4; tn++) {
                    asm volatile(
                        "mma.sync.aligned.m16n8k16.row.col.f32.f16.f16.f32 "
                        "{%0,%1,%2,%3}, {%4,%5,%6,%7}, {%8,%9}, {%0,%1,%2,%3};\n"
                        : "+f"(acc[tm][tn][0]), "+f"(acc[tm][tn][1]),
                          "+f"(acc[tm][tn][2]), "+f"(acc[tm][tn][3])
                        : "r"(a[tm][0]), "r"(a[tm][1]), "r"(a[tm][2]), "r"(a[tm][3]),
                          "r"(b[tn][0]), "r"(b[tn][1]));
                }
        }
        s  = (s  == 2) ? 0 : s + 1;
        ls = (ls == 2) ? 0 : ls + 1;
    }

    // ---- epilogue ----
    const int l4 = lane >> 2;
    const int lm = lane & 3;

    if (MODE == 0 && z == 2) {
        // v output: stage transposed tile in smem, then coalesced gmem stores.
        __half* s16 = (__half*)smem;     // [128 cols][stride 136 halfs of rows]
        __syncthreads();                 // pipeline smem no longer needed
        #pragma unroll
        for (int tm = 0; tm < 4; tm++) {
            const int rl = wm * 64 + tm * 16 + l4;
            #pragma unroll
            for (int tn = 0; tn < 4; tn++) {
                const int cl = wn * 32 + tn * 8 + (lm << 1);
                const float bx = bias[n0 + cl], by = bias[n0 + cl + 1];
                s16[(cl + 0) * 136 + rl]     = __float2half_rn(acc[tm][tn][0] + bx);
                s16[(cl + 1) * 136 + rl]     = __float2half_rn(acc[tm][tn][1] + by);
                s16[(cl + 0) * 136 + rl + 8] = __float2half_rn(acc[tm][tn][2] + bx);
                s16[(cl + 1) * 136 + rl + 8] = __float2half_rn(acc[tm][tn][3] + by);
            }
        }
        __syncthreads();
        __half* T = (__half*)C2v;        // [VD][MROWS]
        #pragma unroll
        for (int t2 = 0; t2 < 8; t2++) {
            const int task = tid + t2 * 256;      // 2048 tasks = 128 cols x 16 chunks
            const int r8 = task & 15;             // 8-row chunk within column
            const int c  = task >> 4;             // 0..127
            uint4 v = *(const uint4*)&s16[c * 136 + r8 * 8];
            *(uint4*)&T[(long long)(n0 + c) * MROWS + m0 + r8 * 8] = v;
        }
        return;
    }

    #pragma unroll
    for (int tm = 0; tm < 4; tm++) {
        const int row = m0 + wm * 64 + tm * 16 + l4;
        float f0 = alpha, f1 = alpha;
        if (MODE == 2) { f0 = alpha * rowscale[row]; f1 = alpha * rowscale[row + 8]; }
        #pragma unroll
        for (int tn = 0; tn < 4; tn++) {
            const int col = n0 + wn * 32 + tn * 8 + (lm << 1);
            if (MODE == 0) {
                const float bx = bias[col], by = bias[col + 1];
                __half* O = (__half*)(z ? C1v : Cv);
                *(__half2*)&O[(long long)row * KD + col] =
                    __floats2half2_rn(acc[tm][tn][0] + bx, acc[tm][tn][1] + by);
                *(__half2*)&O[(long long)(row + 8) * KD + col] =
                    __floats2half2_rn(acc[tm][tn][2] + bx, acc[tm][tn][3] + by);
            } else if (MODE == 1) {
                __half* O = (__half*)Cv + (long long)z * sC;
                *(__half2*)&O[(long long)row * ldc + col] =
                    __floats2half2_rn(acc[tm][tn][0] * f0, acc[tm][tn][1] * f0);
                *(__half2*)&O[(long long)(row + 8) * ldc + col] =
                    __floats2half2_rn(acc[tm][tn][2] * f1, acc[tm][tn][3] * f1);
            } else {
                float* O = (float*)Cv + (long long)z * sC;
                float2 v0, v1;
                v0.x = acc[tm][tn][0] * f0;
                v0.y = acc[tm][tn][1] * f0;
                v1.x = acc[tm][tn][2] * f1;
                v1.y = acc[tm][tn][3] * f1;
                *(float2*)&O[(long long)row * ldc + col]       = v0;
                *(float2*)&O[(long long)(row + 8) * ldc + col] = v1;
            }
        }
    }
}

// ---------------------------------------------------------------------------
// Prep: W[k][n] fp32 -> Wt[z][n][k] fp16, tiled smem transpose (coalesced R+W)
// grid: (KD/32, FEAT/32, 3), block: 32x8
// ---------------------------------------------------------------------------
__global__ __launch_bounds__(256) void cvt_w_kernel(const float* __restrict__ Wq,
                                                    const float* __restrict__ Wk,
                                                    const float* __restrict__ Wv,
                                                    __half* __restrict__ Wt)
{
    __shared__ float tile[32][33];
    const int zz = blockIdx.z;
    const float* W = (zz == 0) ? Wq : (zz == 1) ? Wk : Wv;
    __half* T = Wt + (long long)zz * KD * FEAT;

    const int n0 = blockIdx.x * 32;       // n block
    const int r0 = blockIdx.y * 32;       // k block
    const int tx = threadIdx.x;           // 0..31
    const int ty = threadIdx.y;           // 0..7

    #pragma unroll
    for (int j = 0; j < 4; j++) {
        const int r = ty + j * 8;
        tile[r][tx] = W[(long long)(r0 + r) * KD + n0 + tx];   // coalesced read
    }
    __syncthreads();
    #pragma unroll
    for (int j = 0; j < 4; j++) {
        const int n = ty + j * 8;
        T[(long long)(n0 + n) * FEAT + r0 + tx] = __float2half_rn(tile[tx][n]);  // coalesced write
    }
}

// ---------------------------------------------------------------------------
// Fused: copy x into out[..., 0:FEAT] AND convert x -> fp16 (one read of x)
// ---------------------------------------------------------------------------
__global__ __launch_bounds__(256) void copy_cvt_kernel(const float4* __restrict__ x,
                                                       float4* __restrict__ out,
                                                       uint2* __restrict__ xh)
{
    const long long i = (long long)blockIdx.x * blockDim.x + threadIdx.x;
    const long long total = (long long)MROWS * (FEAT / 4);
    if (i >= total) return;
    const long long row = i / (FEAT / 4);
    const int col = (int)(i % (FEAT / 4));
    float4 v = x[i];
    out[row * (OUTD / 4) + col] = v;
    __half2 h0 = __floats2half2_rn(v.x, v.y);
    __half2 h1 = __floats2half2_rn(v.z, v.w);
    uint2 u;
    u.x = *(uint32_t*)&h0;
    u.y = *(uint32_t*)&h1;
    xh[i] = u;
}

// ---------------------------------------------------------------------------
// Warp-per-row softmax over fp16 logits: max pass + exp pass (fp32 math),
// writes unnormalized fp16 probs (zeros fused to 128-aligned band end);
// rsum = 1/sum.
// ---------------------------------------------------------------------------
__global__ __launch_bounds__(256) void softmax_kernel(const __half* __restrict__ logits,
                                                      __half* __restrict__ probs,
                                                      float* __restrict__ rsum)
{
    const int wid  = threadIdx.x >> 5;
    const int lane = threadIdx.x & 31;
    const long long row = (long long)blockIdx.x * 8 + wid;
    const int q = (int)(row % SEQ);
    const __half* p = logits + row * SEQ;
    const uint2* p4 = (const uint2*)p;              // 4 halfs per element
    uint2* o4 = (uint2*)(probs + row * SEQ);        // 4 halfs per element
    const int len  = q + 1;
    const int len4 = len >> 2;
    const int band4 = (((q >> 7) + 1) << 7) >> 2;   // groups of 4, multiple of 32

    float mx = -INFINITY;
    for (int i = lane; i < len4; i += 32) {
        uint2 u = p4[i];
        const float2 f0 = __half22float2(*(const __half2*)&u.x);
        const float2 f1 = __half22float2(*(const __half2*)&u.y);
        mx = fmaxf(mx, fmaxf(fmaxf(f0.x, f0.y), fmaxf(f1.x, f1.y)));
    }
    for (int i = (len4 << 2) + lane; i < len; i += 32)
        mx = fmaxf(mx, __half2float(p[i]));
    #pragma unroll
    for (int o = 16; o > 0; o >>= 1)
        mx = fmaxf(mx, __shfl_xor_sync(0xffffffffu, mx, o));

    float sum = 0.0f;
    for (int i = lane; i < band4; i += 32) {
        uint2 u = p4[i];
        const float2 f0 = __half22float2(*(const __half2*)&u.x);
        const float2 f1 = __half22float2(*(const __half2*)&u.y);
        const int e = i << 2;
        float w0 = (e     < len) ? __expf(f0.x - mx) : 0.0f;
        float w1 = (e + 1 < len) ? __expf(f0.y - mx) : 0.0f;
        float w2 = (e + 2 < len) ? __expf(f1.x - mx) : 0.0f;
        float w3 = (e + 3 < len) ? __expf(f1.y - mx) : 0.0f;
        sum += (w0 + w1) + (w2 + w3);
        __half2 h0 = __floats2half2_rn(w0, w1);
        __half2 h1 = __floats2half2_rn(w2, w3);
        uint2 o;
        o.x = *(uint32_t*)&h0;
        o.y = *(uint32_t*)&h1;
        o4[i] = o;
    }
    #pragma unroll
    for (int o = 16; o > 0; o >>= 1)
        sum += __shfl_xor_sync(0xffffffffu, sum, o);

    if (lane == 0) rsum[row] = 1.0f / sum;
}

// ---------------------------------------------------------------------------
extern "C" void kernel_launch(void* const* d_in, const int* in_sizes, int n_in,
                              void* d_out, int out_size)
{
    const float* x  = (const float*)d_in[0];
    const float* Wq = (const float*)d_in[1];
    const float* bq = (const float*)d_in[2];
    const float* Wk = (const float*)d_in[3];
    const float* bk = (const float*)d_in[4];
    const float* Wv = (const float*)d_in[5];
    const float* bv = (const float*)d_in[6];
    float* out = (float*)d_out;

    __half *xh, *wt, *qh, *kh, *vt, *ph, *logits;
    float *rsum;
    cudaGetSymbolAddress((void**)&xh,     g_xh);
    cudaGetSymbolAddress((void**)&wt,     g_wt);
    cudaGetSymbolAddress((void**)&qh,     g_qh);
    cudaGetSymbolAddress((void**)&kh,     g_kh);
    cudaGetSymbolAddress((void**)&vt,     g_vt);
    cudaGetSymbolAddress((void**)&ph,     g_ph);
    cudaGetSymbolAddress((void**)&logits, g_logits);
    cudaGetSymbolAddress((void**)&rsum,   g_rsum);

    const float scale = 0.044194173824159216f;  // 1/sqrt(512)

    cudaFuncSetAttribute(mma_gemm<0>, cudaFuncAttributeMaxDynamicSharedMemorySize, SMEM_BYTES);
    cudaFuncSetAttribute(mma_gemm<1>, cudaFuncAttributeMaxDynamicSharedMemorySize, SMEM_BYTES);
    cudaFuncSetAttribute(mma_gemm<2>, cudaFuncAttributeMaxDynamicSharedMemorySize, SMEM_BYTES);

    // prep: x copy+convert (one read), W tiled transpose+convert
    copy_cvt_kernel<<<(int)(((long long)MROWS * (FEAT / 4) + 255) / 256), 256>>>(
        (const float4*)x, (float4*)out, (uint2*)xh);
    {
        dim3 grid(KD / 32, FEAT / 32, 3);
        dim3 blk(32, 8, 1);
        cvt_w_kernel<<<grid, blk>>>(Wq, Wk, Wv, wt);
    }

    // Fused QKV projections (z: q / k / v-transposed)
    {
        dim3 grid(KD / 128, MROWS / 128, 3);
        mma_gemm<0><<<grid, 256, SMEM_BYTES>>>(
            xh, wt, bq, bk, bv, nullptr, qh, kh, vt,
            FEAT, FEAT, 0, FEAT, 0, 0, 0, 1.0f);
    }

    // logits(fp16) = scale * Q @ K^T : triangular grid
    {
        dim3 grid(136, 1, BATCH);
        mma_gemm<1><<<grid, 256, SMEM_BYTES>>>(
            qh, kh, nullptr, nullptr, nullptr, nullptr, logits, nullptr, nullptr,
            KD, KD, SEQ, KD,
            (long long)SEQ * KD, (long long)SEQ * KD, (long long)SEQ * SEQ, scale);
    }

    // softmax: fp16 logits -> fp16 unnormalized probs (+band zero), 1/sum
    softmax_kernel<<<MROWS / 8, 256>>>(logits, ph, rsum);

    // read = (P @ V) * rowscale -> out[..., FEAT:]
    {
        dim3 grid(VD / 128, SEQ / 128, BATCH);
        mma_gemm<2><<<grid, 256, SMEM_BYTES>>>(
            ph, vt, nullptr, nullptr, nullptr, rsum, out + FEAT, nullptr, nullptr,
            SEQ, MROWS, OUTD, SEQ,
            (long long)SEQ * SEQ, SEQ, (long long)SEQ * OUTD, 1.0f);
    }
}